// round 16
// baseline (speedup 1.0000x reference)
#include <cuda_runtime.h>
#include <cstdint>

// ---------------- problem constants ----------------
#define NN    4000        // nodes
#define LL    15000       // sequence length
#define NW    1000        // LL/15 windows
#define EE    128000      // raw edges
#define ETOT  (EE + NN)   // + self loops
#define HEADS 8
#define NHID  64
#define FDIM  512         // HEADS*NHID
#define GHD   64
#define NEGS  0.2f

#define RPB   14          // rows per block
#define NBLK  296         // 2 x 148 SMs exactly; 296*14 = 4144 >= 4000 (clamped)

// ---------------- device scratch (no allocs allowed) ----------------
__device__ float g_gf[NN * GHD];      // geneflow fc1 [4000,64]
__device__ float g_ag[NN * HEADS];    // per-node gene-attn dots
__device__ float g_xl[NN * FDIM];     // conv->gemm output [4000,512]
__device__ float g_af[NN * HEADS];    // per-node feat-attn dots
__device__ int   g_cnt[NN];           // histogram / cursor (zeroed by k_agg2 for replay)
__device__ int   g_rowptr[NN + 1];    // CSR by dst
__device__ int   g_srcs[ETOT];        // src ids sorted by dst
__device__ float g_xl2[NN];           // layer-2 feature scalar
__device__ float g_gf2[NN];           // layer-2 gene scalar

__device__ __forceinline__ float lrelu(float v) { return v > 0.f ? v : NEGS * v; }

__device__ __forceinline__ void fma2(unsigned long long& d, unsigned long long a,
                                     unsigned long long b) {
    asm("fma.rn.f32x2 %0, %1, %2, %0;" : "+l"(d) : "l"(a), "l"(b));
}
__device__ __forceinline__ unsigned long long packrep(float v) {
    unsigned long long o;
    asm("mov.b64 %0, {%1, %1};" : "=l"(o) : "f"(v));
    return o;
}
__device__ __forceinline__ float2 unpack2(unsigned long long v) {
    float2 r;
    asm("mov.b64 {%0, %1}, %2;" : "=f"(r.x), "=f"(r.y) : "l"(v));
    return r;
}
__device__ __forceinline__ unsigned su32(const void* p) {
    return (unsigned)__cvta_generic_to_shared(p);
}
__device__ __forceinline__ void cpa16(unsigned s, const void* g) {
    asm volatile("cp.async.cg.shared.global [%0], [%1], 16;\n" :: "r"(s), "l"(g));
}
// bulk async copy global -> shared with mbarrier transaction accounting (UBLKCP)
__device__ __forceinline__ void bulkcp(unsigned dst, const void* src, unsigned bytes,
                                       unsigned mbar) {
    asm volatile(
        "cp.async.bulk.shared::cluster.global.mbarrier::complete_tx::bytes "
        "[%0], [%1], %2, [%3];"
        :: "r"(dst), "l"(src), "r"(bytes), "r"(mbar) : "memory");
}
__device__ __forceinline__ void mbar_init(unsigned mbar, unsigned cnt) {
    asm volatile("mbarrier.init.shared.b64 [%0], %1;" :: "r"(mbar), "r"(cnt) : "memory");
}
__device__ __forceinline__ void mbar_expect(unsigned mbar, unsigned bytes) {
    asm volatile("mbarrier.arrive.expect_tx.shared.b64 _, [%0], %1;"
                 :: "r"(mbar), "r"(bytes) : "memory");
}
__device__ __forceinline__ void mbar_wait(unsigned mbar, unsigned phase) {
    asm volatile(
        "{\n\t.reg .pred P;\n\t"
        "WL_%=:\n\t"
        "mbarrier.try_wait.parity.acquire.cta.shared::cta.b64 P, [%0], %1, 0x989680;\n\t"
        "@P bra WD_%=;\n\t"
        "bra WL_%=;\n\t"
        "WD_%=:\n\t}"
        :: "r"(mbar), "r"(phase) : "memory");
}

// ---------------- fused conv + GEMM + attention-dot epilogue ----------------
// grid 296 (14 rows each), block 256, 2 blocks/SM (balanced wave).
// x: TRIPLE-buffered cp.async (2 tiles ~54KB in flight; wait_group 2).
// W1: double-buffered 16KB cp.async.bulk + mbarrier (L2-resident; 1-tile lookahead).
// smem layout (floats):
#define XSTG  (RPB * 4 * 120)         // 6720 floats per x stage (26880 B)
#define SX0   0                       // 3 x-stages: buf*XSTG
#define SB0   (3 * XSTG)              // 20160; 2 B-stages of 4096 floats each
#define SAS   (SB0 + 2 * 4096)        // 28352
#define SCW   (SAS + 128)             // 28480
#define SMB   (SCW + 20)              // 2 mbarriers (16 B, 8B-aligned)
#define SMEM_FLOATS (SCW + 24)        // 28504 -> 114016 bytes (x2 = 228 KB/SM)
#define W1_TILE_BYTES 16384

__global__ void __launch_bounds__(256, 2) k_convgemm(
    const float* __restrict__ x,
    const float* __restrict__ cjw, const float* __restrict__ cjb,
    const float* __restrict__ cj2w, const float* __restrict__ cj2b,
    const float* __restrict__ W1, const float* __restrict__ b1,
    const float* __restrict__ att1f) {
    extern __shared__ float sm[];
    int t = threadIdx.x;
    int n0 = blockIdx.x * RPB;
    int warp = t >> 5, lane = t & 31;
    int cOff = warp * 64 + lane * 2;   // thread's 2 columns; head = warp

    unsigned mbar0 = su32(sm + SMB);
    unsigned mbar1 = su32(sm + SMB + 2);

    // stage conv weights into smem; init mbarriers
    if (t < 4) sm[SCW + t] = cjw[t];
    if (t < 15) sm[SCW + 4 + t] = cj2w[t];
    if (t == 0) {
        float ws = 0.f;
        for (int k = 0; k < 15; k++) ws += cj2w[k];
        sm[SCW + 19] = cjb[0] * ws + cj2b[0];
        mbar_init(mbar0, 1);
        mbar_init(mbar1, 1);
    }
    __syncthreads();

    // ---- x issuer: per-thread cp.async into x-stage buf (0..2) ----
    auto issueX = [&](int tile, int buf) {
        float* xb = sm + buf * XSTG;
#pragma unroll
        for (int r = 0; r < 6; r++) {
            int chunk = t + r * 256;          // 0..1535
            int rowch = chunk / 30;           // 0..55  (c*14 + row)
            int ofs = chunk - rowch * 30;     // 0..29
            int c = rowch / RPB, row = rowch - c * RPB;
            int gr = n0 + row; if (gr >= NN) gr = NN - 1;
            const float* g = x + ((size_t)gr * 4 + c) * LL + tile * 120 + ofs * 4;
            cpa16(su32(xb + rowch * 120 + ofs * 4), g);
        }
        if (t < 144) {
            int chunk = 1536 + t;             // 1536..1679
            int rowch = chunk / 30;
            int ofs = chunk - rowch * 30;
            int c = rowch / RPB, row = rowch - c * RPB;
            int gr = n0 + row; if (gr >= NN) gr = NN - 1;
            const float* g = x + ((size_t)gr * 4 + c) * LL + tile * 120 + ofs * 4;
            cpa16(su32(xb + rowch * 120 + ofs * 4), g);
        }
        asm volatile("cp.async.commit_group;\n");
    };
    // ---- W1 issuer: one contiguous 16KB bulk copy into B-stage (0..1), t0 only ----
    auto issueB = [&](int tile) {
        if (t != 0) return;
        int b = tile & 1;
        unsigned mb = b ? mbar1 : mbar0;
        mbar_expect(mb, W1_TILE_BYTES);
        bulkcp(su32(sm + SB0 + b * 4096), W1 + (size_t)tile * 8 * FDIM,
               W1_TILE_BYTES, mb);
    };

    issueX(0, 0);
    issueX(1, 1);
    issueB(0);

    // conv weights to registers (persist across loop)
    float cwv[4], c2[15], cst;
    __syncthreads();
#pragma unroll
    for (int c = 0; c < 4; c++) cwv[c] = sm[SCW + c];
#pragma unroll
    for (int k = 0; k < 15; k++) c2[k] = sm[SCW + 4 + k];
    cst = sm[SCW + 19];

    unsigned long long acc[7][2];   // row-pair rp (rows 2rp,2rp+1) x 2 cols
#pragma unroll
    for (int i = 0; i < 7; i++) { acc[i][0] = 0ull; acc[i][1] = 0ull; }

    int crow = t >> 3, cwin = t & 7;   // conv: threads 0..111 -> 14 rows x 8 windows

    int buf = 0;
    for (int tile = 0; tile < 125; tile++) {
        // issue W1 for next tile (buffer (tile+1)&1 != current read buffer)
        if (tile < 124) issueB(tile + 1);
        // issue x for tile+2 into (buf+2)%3 = (tile-1)%3 buffer (reader done)
        if (tile < 123) {
            int b2 = buf + 2; if (b2 >= 3) b2 -= 3;
            issueX(tile + 2, b2);
            asm volatile("cp.async.wait_group 2;\n");
        } else if (tile == 123) {
            asm volatile("cp.async.wait_group 1;\n");
        } else {
            asm volatile("cp.async.wait_group 0;\n");
        }
        __syncthreads();

        // conv: threads 0..111 -> 14 rows x 8 windows
        if (t < RPB * 8) {
            const float* xb = sm + buf * XSTG;
            float hv = 0.f;
#pragma unroll
            for (int c = 0; c < 4; c++) {
                const float* p = xb + (c * RPB + crow) * 120 + cwin * 15;
                float s0 = 0.f;
#pragma unroll
                for (int k = 0; k < 15; k++) s0 += c2[k] * p[k];
                hv += cwv[c] * s0;
            }
            sm[SAS + cwin * 16 + crow] = hv + cst;
        }
        __syncthreads();

        // W1 tile ready? (phase flips every 2 tiles per buffer)
        mbar_wait((tile & 1) ? mbar1 : mbar0, (tile >> 1) & 1);

        // gemm: 8 k-steps; thread = 14 rows (7 pairs) x 2 cols
        const float* bb = sm + SB0 + (tile & 1) * 4096;
#pragma unroll
        for (int k = 0; k < 8; k++) {
            float2 bvf = *(const float2*)(bb + k * 512 + cOff);
            unsigned long long b0 = packrep(bvf.x), b1r = packrep(bvf.y);
            const float* as = sm + SAS + k * 16;
            ulonglong2 a01 = *(const ulonglong2*)(as + 0);   // rows 0-3 paired
            ulonglong2 a23 = *(const ulonglong2*)(as + 4);   // rows 4-7
            ulonglong2 a45 = *(const ulonglong2*)(as + 8);   // rows 8-11
            unsigned long long a6 = *(const unsigned long long*)(as + 12);  // rows 12-13
            fma2(acc[0][0], a01.x, b0); fma2(acc[0][1], a01.x, b1r);
            fma2(acc[1][0], a01.y, b0); fma2(acc[1][1], a01.y, b1r);
            fma2(acc[2][0], a23.x, b0); fma2(acc[2][1], a23.x, b1r);
            fma2(acc[3][0], a23.y, b0); fma2(acc[3][1], a23.y, b1r);
            fma2(acc[4][0], a45.x, b0); fma2(acc[4][1], a45.x, b1r);
            fma2(acc[5][0], a45.y, b0); fma2(acc[5][1], a45.y, b1r);
            fma2(acc[6][0], a6,    b0); fma2(acc[6][1], a6,    b1r);
        }
        __syncthreads();   // fences x-buffer and B-buffer reuse
        buf = (buf == 2) ? 0 : buf + 1;
    }

    // epilogue: +b1, store g_xl, fused attention dots g_af (head = warp)
    float2 b1v = *(const float2*)&b1[cOff];
    float2 afw = *(const float2*)&att1f[cOff];
#pragma unroll
    for (int rp = 0; rp < 7; rp++) {
        float2 v0 = unpack2(acc[rp][0]);   // col cOff:   {row 2rp, row 2rp+1}
        float2 v1 = unpack2(acc[rp][1]);   // col cOff+1
        int m0 = n0 + 2 * rp, m1 = m0 + 1;
        float o00 = v0.x + b1v.x, o01 = v1.x + b1v.y;  // row m0
        float o10 = v0.y + b1v.x, o11 = v1.y + b1v.y;  // row m1
        if (m0 < NN) *(float2*)&g_xl[(size_t)m0 * FDIM + cOff] = make_float2(o00, o01);
        if (m1 < NN) *(float2*)&g_xl[(size_t)m1 * FDIM + cOff] = make_float2(o10, o11);
        float va = o00 * afw.x + o01 * afw.y;
        float vb = o10 * afw.x + o11 * afw.y;
#pragma unroll
        for (int off = 16; off; off >>= 1) {
            va += __shfl_down_sync(0xffffffffu, va, off);
            vb += __shfl_down_sync(0xffffffffu, vb, off);
        }
        if (lane == 0) {
            if (m0 < NN) g_af[m0 * 8 + warp] = va;
            if (m1 < NN) g_af[m1 * 8 + warp] = vb;
        }
    }
}

// ---------------- geneflow fc1 + per-node gene attention dots ----------------
// grid 1000, block 256 = 4 nodes x 64 channels
__global__ void k_gf(const float* __restrict__ gfin, const float* __restrict__ fc1w,
                     const float* __restrict__ fc1b, const float* __restrict__ att1g) {
    __shared__ float gin[4][64], gout[4][64];
    int t = threadIdx.x;
    int ln = t >> 6, c = t & 63;
    int n = blockIdx.x * 4 + ln;
    gin[ln][c] = gfin[n * 64 + c];
    __syncthreads();
    float acc = fc1b[c];
#pragma unroll 8
    for (int i = 0; i < 64; i++) acc += gin[ln][i] * fc1w[i * GHD + c];
    g_gf[n * GHD + c] = acc;
    gout[ln][c] = acc;
    __syncthreads();
    if (c < HEADS) {
        float a = 0.f;
#pragma unroll 8
        for (int g = 0; g < GHD; g++) a += gout[ln][g] * att1g[c * GHD + g];
        g_ag[n * HEADS + c] = a;
    }
}

// ---------------- CSR build ----------------
// g_cnt is zero before each run (zero-init at load; reset by k_agg2 each replay).
__global__ void k_hist(const int* __restrict__ ei) {
    int e = blockIdx.x * blockDim.x + threadIdx.x;
    if (e < EE) atomicAdd(&g_cnt[ei[EE + e]], 1);
}
__global__ void k_scan() {  // 1 block, 1024 threads, 4 elems each; +1 = self loop
    __shared__ int sums[1024];
    int tid = threadIdx.x;
    int base = tid * 4;
    int v0 = 0, v1 = 0, v2 = 0, v3 = 0;
    if (base + 0 < NN) v0 = g_cnt[base + 0] + 1;
    if (base + 1 < NN) v1 = g_cnt[base + 1] + 1;
    if (base + 2 < NN) v2 = g_cnt[base + 2] + 1;
    if (base + 3 < NN) v3 = g_cnt[base + 3] + 1;
    sums[tid] = v0 + v1 + v2 + v3;
    __syncthreads();
    for (int off = 1; off < 1024; off <<= 1) {
        int add = (tid >= off) ? sums[tid - off] : 0;
        __syncthreads();
        sums[tid] += add;
        __syncthreads();
    }
    int run = tid ? sums[tid - 1] : 0;
    if (base + 0 < NN) { g_rowptr[base + 0] = run; g_cnt[base + 0] = run; run += v0; }
    if (base + 1 < NN) { g_rowptr[base + 1] = run; g_cnt[base + 1] = run; run += v1; }
    if (base + 2 < NN) { g_rowptr[base + 2] = run; g_cnt[base + 2] = run; run += v2; }
    if (base + 3 < NN) { g_rowptr[base + 3] = run; g_cnt[base + 3] = run; run += v3; }
    if (tid == 1023) g_rowptr[NN] = sums[1023];
}
__global__ void k_scatter(const int* __restrict__ ei) {
    int e = blockIdx.x * blockDim.x + threadIdx.x;
    if (e >= ETOT) return;
    int s, d;
    if (e < EE) { s = ei[e]; d = ei[EE + e]; }
    else        { s = d = e - EE; }
    int p = atomicAdd(&g_cnt[d], 1);
    g_srcs[p] = s;
}

// ---------------- layer-1: SINGLE-PASS attention + aggregation + fused epilogue ----
// thread t = head h * 64 + channel c
__global__ void __launch_bounds__(512) k_agg1(
    const float* __restrict__ bias1f, const float* __restrict__ bias1g,
    const float* __restrict__ W2, const float* __restrict__ b2,
    const float* __restrict__ fc2w, const float* __restrict__ fc2b) {
    __shared__ float afn[8], agn[8];
    __shared__ int   ssrc[128];
    __shared__ float w1s[128 * 8];   // exp(feature logit) per edge per head
    __shared__ float w2s[128 * 8];   // exp(gene logit)    per edge per head
    __shared__ float s12[16];        // s1[0..7], s2[8..15]
    __shared__ float gacc[8][64];
    __shared__ float red[16];

    int n = blockIdx.x, t = threadIdx.x;
    int base = g_rowptr[n];
    int deg  = g_rowptr[n + 1] - base;
    int w = t >> 5, lane = t & 31;
    int h = t >> 6, c = t & 63;

    if (t < 8) { afn[t] = g_af[n * 8 + t]; agn[t] = g_ag[n * 8 + t]; }
    __syncthreads();

    float accf = 0.f, accg = 0.f, s1p = 0.f, s2p = 0.f;
    for (int c0 = 0; c0 < deg; c0 += 128) {
        int clen = min(128, deg - c0);
        if (t < clen) ssrc[t] = g_srcs[base + c0 + t];
        __syncthreads();
        if (t < clen) {
            int s = ssrc[t];
#pragma unroll
            for (int hh = 0; hh < 8; hh++) {
                w1s[t * 8 + hh] = __expf(lrelu(afn[hh] + g_af[s * 8 + hh]));
                w2s[t * 8 + hh] = __expf(lrelu(agn[hh] + g_ag[s * 8 + hh]));
            }
        }
        __syncthreads();
#pragma unroll 4
        for (int e = 0; e < clen; e++) {
            int s = ssrc[e];
            float w1v = w1s[e * 8 + h];
            float w2v = w2s[e * 8 + h];
            accf += w2v * g_xl[s * FDIM + t];   // features weighted by gene attn
            accg += w1v * g_gf[s * GHD + c];    // gene weighted by feature attn
            s1p += w1v;
            s2p += w2v;
        }
        __syncthreads();
    }

    if (c == 0) { s12[h] = s1p; s12[8 + h] = s2p; }
    __syncthreads();

    // feature epilogue: normalize, relu, h1@W2+b2 (block reduce)
    float o = fmaxf(accf / s12[8 + h] + bias1f[t], 0.f);
    float v = o * W2[t];
#pragma unroll
    for (int off = 16; off; off >>= 1) v += __shfl_down_sync(0xffffffffu, v, off);
    if (lane == 0) red[w] = v;
    // gene epilogue: per-head normalized partials to shared
    gacc[h][c] = accg / s12[h];
    __syncthreads();
    if (t < 16) {
        float r = red[t];
#pragma unroll
        for (int off = 8; off; off >>= 1) r += __shfl_down_sync(0x0000ffffu, r, off);
        if (t == 0) g_xl2[n] = r + b2[0];
    }
    float gv = 0.f;
    if (t < 64) {
        float g1 = 0.f;
#pragma unroll
        for (int hh = 0; hh < 8; hh++) g1 += gacc[hh][t];
        g1 = fmaxf(g1 * 0.125f + bias1g[t], 0.f);
        gv = g1 * fc2w[t];
#pragma unroll
        for (int off = 16; off; off >>= 1) gv += __shfl_down_sync(0xffffffffu, gv, off);
    }
    __syncthreads();
    if (t < 64 && lane == 0) red[w] = gv;
    __syncthreads();
    if (t == 0) g_gf2[n] = red[0] + red[1] + fc2b[0];
}

// ---------------- layer 2: single-pass + final sigmoid, warp per node ----------------
// Also resets g_cnt[n] = 0 for the next graph replay (determinism).
__global__ void k_agg2(float* __restrict__ out,
                       const float* __restrict__ att2f, const float* __restrict__ att2g,
                       const float* __restrict__ bias2f, const float* __restrict__ bias2g) {
    int gwarp = (blockIdx.x * blockDim.x + threadIdx.x) >> 5;
    int lane = threadIdx.x & 31;
    if (gwarp >= NN) return;
    int n = gwarp;
    if (lane == 1) g_cnt[n] = 0;   // reset histogram for next replay
    float taf = att2f[0], tag = att2g[0];
    int base = g_rowptr[n], deg = g_rowptr[n + 1] - base;
    float xn = g_xl2[n], gn = g_gf2[n];
    float s1 = 0.f, s2 = 0.f, hf = 0.f, hg = 0.f;
    for (int e = lane; e < deg; e += 32) {
        int s = g_srcs[base + e];
        float xs = g_xl2[s], gs = g_gf2[s];
        float e1 = __expf(lrelu(taf * (xn + xs)));
        float e2 = __expf(lrelu(tag * (gn + gs)));
        s1 += e1; s2 += e2;
        hf += e2 * xs;   // feature msg weighted by gene attention
        hg += e1 * gs;   // gene msg weighted by feature attention
    }
#pragma unroll
    for (int off = 16; off; off >>= 1) {
        s1 += __shfl_xor_sync(0xffffffffu, s1, off);
        s2 += __shfl_xor_sync(0xffffffffu, s2, off);
        hf += __shfl_xor_sync(0xffffffffu, hf, off);
        hg += __shfl_xor_sync(0xffffffffu, hg, off);
    }
    if (lane == 0) {
        float h2  = hf / s2 + bias2f[0];
        float gf3 = hg / s1 + bias2g[0];
        float z = h2 + gf3;
        out[n] = 1.f / (1.f + __expf(-z));
    }
}

// ---------------- launcher: single stream ----------------
extern "C" void kernel_launch(void* const* d_in, const int* in_sizes, int n_in,
                              void* d_out, int out_size) {
    const float* x      = (const float*)d_in[0];
    const float* gfin   = (const float*)d_in[1];
    const int*   ei     = (const int*)d_in[2];
    const float* cjw    = (const float*)d_in[3];
    const float* cjb    = (const float*)d_in[4];
    const float* cj2w   = (const float*)d_in[5];
    const float* cj2b   = (const float*)d_in[6];
    const float* fc1w   = (const float*)d_in[7];
    const float* fc1b   = (const float*)d_in[8];
    const float* fc2w   = (const float*)d_in[9];
    const float* fc2b   = (const float*)d_in[10];
    const float* W1     = (const float*)d_in[11];
    const float* b1     = (const float*)d_in[12];
    const float* att1f  = (const float*)d_in[13];
    const float* att1g  = (const float*)d_in[14];
    const float* bias1f = (const float*)d_in[15];
    const float* bias1g = (const float*)d_in[16];
    const float* W2     = (const float*)d_in[17];
    const float* b2     = (const float*)d_in[18];
    const float* att2f  = (const float*)d_in[19];
    const float* att2g  = (const float*)d_in[20];
    const float* bias2f = (const float*)d_in[21];
    const float* bias2g = (const float*)d_in[22];
    float* out = (float*)d_out;

    static bool attrSet = false;
    if (!attrSet) {
        cudaFuncSetAttribute(k_convgemm, cudaFuncAttributeMaxDynamicSharedMemorySize,
                             SMEM_FLOATS * 4);
        attrSet = true;
    }

    // order chosen so k_convgemm is the 4th launch (ncu capture slot)
    k_hist<<<(EE + 255) / 256, 256>>>(ei);
    k_scan<<<1, 1024>>>();
    k_scatter<<<(ETOT + 255) / 256, 256>>>(ei);
    k_convgemm<<<NBLK, 256, SMEM_FLOATS * 4>>>(x, cjw, cjb, cj2w, cj2b, W1, b1, att1f);
    k_gf<<<NN / 4, 256>>>(gfin, fc1w, fc1b, att1g);
    k_agg1<<<NN, 512>>>(bias1f, bias1g, W2, b2, fc2w, fc2b);
    k_agg2<<<(NN * 32 + 255) / 256, 256>>>(out, att2f, att2g, bias2f, bias2g);
}

// round 17
// speedup vs baseline: 1.0911x; 1.0911x over previous
#include <cuda_runtime.h>
#include <cstdint>

// ---------------- problem constants ----------------
#define NN    4000        // nodes
#define LL    15000       // sequence length
#define NW    1000        // LL/15 windows
#define EE    128000      // raw edges
#define ETOT  (EE + NN)   // + self loops
#define HEADS 8
#define NHID  64
#define FDIM  512         // HEADS*NHID
#define GHD   64
#define NEGS  0.2f

#define RPB   14          // rows per block
#define NBLK  296         // 2 x 148 SMs exactly; 296*14 = 4144 >= 4000 (clamped)

// ---------------- device scratch (no allocs allowed) ----------------
__device__ float g_gf[NN * GHD];      // geneflow fc1 [4000,64]
__device__ float g_ag[NN * HEADS];    // per-node gene-attn dots
__device__ float g_xl[NN * FDIM];     // conv->gemm output [4000,512]
__device__ float g_af[NN * HEADS];    // per-node feat-attn dots
__device__ int   g_cnt[NN];           // histogram / cursor (zeroed by k_agg2 for replay)
__device__ int   g_rowptr[NN + 1];    // CSR by dst
__device__ int   g_srcs[ETOT];        // src ids sorted by dst
__device__ float g_xl2[NN];           // layer-2 feature scalar
__device__ float g_gf2[NN];           // layer-2 gene scalar

__device__ __forceinline__ float lrelu(float v) { return v > 0.f ? v : NEGS * v; }

__device__ __forceinline__ void fma2(unsigned long long& d, unsigned long long a,
                                     unsigned long long b) {
    asm("fma.rn.f32x2 %0, %1, %2, %0;" : "+l"(d) : "l"(a), "l"(b));
}
__device__ __forceinline__ unsigned long long packrep(float v) {
    unsigned long long o;
    asm("mov.b64 %0, {%1, %1};" : "=l"(o) : "f"(v));
    return o;
}
__device__ __forceinline__ float2 unpack2(unsigned long long v) {
    float2 r;
    asm("mov.b64 {%0, %1}, %2;" : "=f"(r.x), "=f"(r.y) : "l"(v));
    return r;
}
__device__ __forceinline__ unsigned su32(const void* p) {
    return (unsigned)__cvta_generic_to_shared(p);
}
__device__ __forceinline__ void cpa16(unsigned s, const void* g) {
    asm volatile("cp.async.cg.shared.global [%0], [%1], 16;\n" :: "r"(s), "l"(g));
}

// ---------------- fused conv + GEMM + attention-dot epilogue ----------------
// ROUND-12 committed version (184.9us, structural DRAM cap ~66%).
// grid 296 (14 rows each), block 256, 2 blocks/SM, double-buffered cp.async.
// smem layout (floats):
#define XSTG  (RPB * 4 * 120)         // 6720 floats per x stage
#define SX0   0
#define SX1   XSTG
#define SB0   (2 * XSTG)              // 13440
#define SB1   (SB0 + 4096)            // 17536
#define SAS   (SB1 + 4096)            // 21632 (8k x stride16 = 128 floats)
#define SCW   (SAS + 128)             // 21760
#define SMEM_FLOATS (SCW + 24)        // 21784 -> 87136 bytes

__global__ void __launch_bounds__(256, 2) k_convgemm(
    const float* __restrict__ x,
    const float* __restrict__ cjw, const float* __restrict__ cjb,
    const float* __restrict__ cj2w, const float* __restrict__ cj2b,
    const float* __restrict__ W1, const float* __restrict__ b1,
    const float* __restrict__ att1f) {
    extern __shared__ float sm[];
    int t = threadIdx.x;
    int n0 = blockIdx.x * RPB;
    int warp = t >> 5, lane = t & 31;
    int cOff = warp * 64 + lane * 2;   // thread's 2 columns; head = warp

    // stage conv weights into smem
    if (t < 4) sm[SCW + t] = cjw[t];
    if (t < 15) sm[SCW + 4 + t] = cj2w[t];
    if (t == 0) {
        float ws = 0.f;
        for (int k = 0; k < 15; k++) ws += cj2w[k];
        sm[SCW + 19] = cjb[0] * ws + cj2b[0];
    }

    // ---- async copy issuer for tile -> buffer ----
    auto issue = [&](int tile, int buf) {
        float* xb = sm + (buf ? SX1 : SX0);
        float* bb = sm + (buf ? SB1 : SB0);
        // x: 14 rows x 4 ch x 30 16B-chunks = 1680 chunks
#pragma unroll
        for (int r = 0; r < 6; r++) {
            int chunk = t + r * 256;          // 0..1535
            int rowch = chunk / 30;           // 0..55  (c*14 + row)
            int ofs = chunk - rowch * 30;     // 0..29
            int c = rowch / RPB, row = rowch - c * RPB;
            int gr = n0 + row; if (gr >= NN) gr = NN - 1;
            const float* g = x + ((size_t)gr * 4 + c) * LL + tile * 120 + ofs * 4;
            cpa16(su32(xb + rowch * 120 + ofs * 4), g);
        }
        if (t < 144) {
            int chunk = 1536 + t;             // 1536..1679
            int rowch = chunk / 30;
            int ofs = chunk - rowch * 30;
            int c = rowch / RPB, row = rowch - c * RPB;
            int gr = n0 + row; if (gr >= NN) gr = NN - 1;
            const float* g = x + ((size_t)gr * 4 + c) * LL + tile * 120 + ofs * 4;
            cpa16(su32(xb + rowch * 120 + ofs * 4), g);
        }
        // W1 k-tile: 8 x 512 floats = 1024 chunks
#pragma unroll
        for (int r = 0; r < 4; r++) {
            int chunk = t + r * 256;
            int k = chunk >> 7, col4 = (chunk & 127) * 4;
            const float* g = W1 + (size_t)(tile * 8 + k) * FDIM + col4;
            cpa16(su32(bb + k * 512 + col4), g);
        }
        asm volatile("cp.async.commit_group;\n");
    };

    issue(0, 0);
    __syncthreads();

    // conv weights to registers (persist across loop)
    float cwv[4], c2[15], cst;
#pragma unroll
    for (int c = 0; c < 4; c++) cwv[c] = sm[SCW + c];
#pragma unroll
    for (int k = 0; k < 15; k++) c2[k] = sm[SCW + 4 + k];
    cst = sm[SCW + 19];

    unsigned long long acc[7][2];   // row-pair rp (rows 2rp,2rp+1) x 2 cols
#pragma unroll
    for (int i = 0; i < 7; i++) { acc[i][0] = 0ull; acc[i][1] = 0ull; }

    int crow = t >> 3, cwin = t & 7;   // conv: threads 0..111 -> 14 rows x 8 windows

    for (int tile = 0; tile < 125; tile++) {
        int buf = tile & 1;
        if (tile < 124) {
            issue(tile + 1, buf ^ 1);
            asm volatile("cp.async.wait_group 1;\n");
        } else {
            asm volatile("cp.async.wait_group 0;\n");
        }
        __syncthreads();

        // conv: threads 0..111 -> 14 rows x 8 windows
        if (t < RPB * 8) {
            const float* xb = sm + (buf ? SX1 : SX0);
            float hv = 0.f;
#pragma unroll
            for (int c = 0; c < 4; c++) {
                const float* p = xb + (c * RPB + crow) * 120 + cwin * 15;
                float s0 = 0.f;
#pragma unroll
                for (int k = 0; k < 15; k++) s0 += c2[k] * p[k];
                hv += cwv[c] * s0;
            }
            sm[SAS + cwin * 16 + crow] = hv + cst;
        }
        __syncthreads();

        // gemm: 8 k-steps; thread = 14 rows (7 pairs) x 2 cols
        const float* bb = sm + (buf ? SB1 : SB0);
#pragma unroll
        for (int k = 0; k < 8; k++) {
            float2 bvf = *(const float2*)(bb + k * 512 + cOff);
            unsigned long long b0 = packrep(bvf.x), b1r = packrep(bvf.y);
            const float* as = sm + SAS + k * 16;
            ulonglong2 a01 = *(const ulonglong2*)(as + 0);   // rows 0-3 paired
            ulonglong2 a23 = *(const ulonglong2*)(as + 4);   // rows 4-7
            ulonglong2 a45 = *(const ulonglong2*)(as + 8);   // rows 8-11
            unsigned long long a6 = *(const unsigned long long*)(as + 12);  // rows 12-13
            fma2(acc[0][0], a01.x, b0); fma2(acc[0][1], a01.x, b1r);
            fma2(acc[1][0], a01.y, b0); fma2(acc[1][1], a01.y, b1r);
            fma2(acc[2][0], a23.x, b0); fma2(acc[2][1], a23.x, b1r);
            fma2(acc[3][0], a23.y, b0); fma2(acc[3][1], a23.y, b1r);
            fma2(acc[4][0], a45.x, b0); fma2(acc[4][1], a45.x, b1r);
            fma2(acc[5][0], a45.y, b0); fma2(acc[5][1], a45.y, b1r);
            fma2(acc[6][0], a6,    b0); fma2(acc[6][1], a6,    b1r);
        }
        __syncthreads();
    }

    // epilogue: +b1, store g_xl, fused attention dots g_af (head = warp)
    float2 b1v = *(const float2*)&b1[cOff];
    float2 afw = *(const float2*)&att1f[cOff];
#pragma unroll
    for (int rp = 0; rp < 7; rp++) {
        float2 v0 = unpack2(acc[rp][0]);   // col cOff:   {row 2rp, row 2rp+1}
        float2 v1 = unpack2(acc[rp][1]);   // col cOff+1
        int m0 = n0 + 2 * rp, m1 = m0 + 1;
        float o00 = v0.x + b1v.x, o01 = v1.x + b1v.y;  // row m0
        float o10 = v0.y + b1v.x, o11 = v1.y + b1v.y;  // row m1
        if (m0 < NN) *(float2*)&g_xl[(size_t)m0 * FDIM + cOff] = make_float2(o00, o01);
        if (m1 < NN) *(float2*)&g_xl[(size_t)m1 * FDIM + cOff] = make_float2(o10, o11);
        float va = o00 * afw.x + o01 * afw.y;
        float vb = o10 * afw.x + o11 * afw.y;
#pragma unroll
        for (int off = 16; off; off >>= 1) {
            va += __shfl_down_sync(0xffffffffu, va, off);
            vb += __shfl_down_sync(0xffffffffu, vb, off);
        }
        if (lane == 0) {
            if (m0 < NN) g_af[m0 * 8 + warp] = va;
            if (m1 < NN) g_af[m1 * 8 + warp] = vb;
        }
    }
}

// ---------------- geneflow fc1 + per-node gene attention dots ----------------
// grid 1000, block 256 = 4 nodes x 64 channels
__global__ void k_gf(const float* __restrict__ gfin, const float* __restrict__ fc1w,
                     const float* __restrict__ fc1b, const float* __restrict__ att1g) {
    __shared__ float gin[4][64], gout[4][64];
    int t = threadIdx.x;
    int ln = t >> 6, c = t & 63;
    int n = blockIdx.x * 4 + ln;
    gin[ln][c] = gfin[n * 64 + c];
    __syncthreads();
    float acc = fc1b[c];
#pragma unroll 8
    for (int i = 0; i < 64; i++) acc += gin[ln][i] * fc1w[i * GHD + c];
    g_gf[n * GHD + c] = acc;
    gout[ln][c] = acc;
    __syncthreads();
    if (c < HEADS) {
        float a = 0.f;
#pragma unroll 8
        for (int g = 0; g < GHD; g++) a += gout[ln][g] * att1g[c * GHD + g];
        g_ag[n * HEADS + c] = a;
    }
}

// ---------------- CSR build ----------------
// g_cnt is zero before each run (zero-init at load; reset by k_agg2 each replay).
__global__ void k_hist(const int* __restrict__ ei) {
    int e = blockIdx.x * blockDim.x + threadIdx.x;
    if (e < EE) atomicAdd(&g_cnt[ei[EE + e]], 1);
}
__global__ void k_scan() {  // 1 block, 1024 threads, 4 elems each; +1 = self loop
    __shared__ int sums[1024];
    int tid = threadIdx.x;
    int base = tid * 4;
    int v0 = 0, v1 = 0, v2 = 0, v3 = 0;
    if (base + 0 < NN) v0 = g_cnt[base + 0] + 1;
    if (base + 1 < NN) v1 = g_cnt[base + 1] + 1;
    if (base + 2 < NN) v2 = g_cnt[base + 2] + 1;
    if (base + 3 < NN) v3 = g_cnt[base + 3] + 1;
    sums[tid] = v0 + v1 + v2 + v3;
    __syncthreads();
    for (int off = 1; off < 1024; off <<= 1) {
        int add = (tid >= off) ? sums[tid - off] : 0;
        __syncthreads();
        sums[tid] += add;
        __syncthreads();
    }
    int run = tid ? sums[tid - 1] : 0;
    if (base + 0 < NN) { g_rowptr[base + 0] = run; g_cnt[base + 0] = run; run += v0; }
    if (base + 1 < NN) { g_rowptr[base + 1] = run; g_cnt[base + 1] = run; run += v1; }
    if (base + 2 < NN) { g_rowptr[base + 2] = run; g_cnt[base + 2] = run; run += v2; }
    if (base + 3 < NN) { g_rowptr[base + 3] = run; g_cnt[base + 3] = run; run += v3; }
    if (tid == 1023) g_rowptr[NN] = sums[1023];
}
__global__ void k_scatter(const int* __restrict__ ei) {
    int e = blockIdx.x * blockDim.x + threadIdx.x;
    if (e >= ETOT) return;
    int s, d;
    if (e < EE) { s = ei[e]; d = ei[EE + e]; }
    else        { s = d = e - EE; }
    int p = atomicAdd(&g_cnt[d], 1);
    g_srcs[p] = s;
}

// ---------------- layer-1: single-pass attention + aggregation, float2 lanes ----
// 256 threads: warp w = head h (0..7); lane covers 2 channels (c2 = lane*2).
// Halves LSU instruction count vs the 512-thread scalar version (LDG.64 loads).
__global__ void __launch_bounds__(256) k_agg1(
    const float* __restrict__ bias1f, const float* __restrict__ bias1g,
    const float* __restrict__ W2, const float* __restrict__ b2,
    const float* __restrict__ fc2w, const float* __restrict__ fc2b) {
    __shared__ float afn[8], agn[8];
    __shared__ int   ssrc[128];
    __shared__ float w1s[128 * 8];   // exp(feature logit) per edge per head
    __shared__ float w2s[128 * 8];   // exp(gene logit)    per edge per head
    __shared__ float s12[16];        // s1[0..7], s2[8..15]
    __shared__ float gacc[8][64];
    __shared__ float red[8];

    int n = blockIdx.x, t = threadIdx.x;
    int base = g_rowptr[n];
    int deg  = g_rowptr[n + 1] - base;
    int h = t >> 5, lane = t & 31;   // head = warp
    int c2 = lane * 2;               // 2 gene channels
    int colg = h * 64 + c2;          // 2 feature columns

    if (t < 8) { afn[t] = g_af[n * 8 + t]; agn[t] = g_ag[n * 8 + t]; }
    __syncthreads();

    float2 accf = make_float2(0.f, 0.f), accg = make_float2(0.f, 0.f);
    float s1p = 0.f, s2p = 0.f;
    for (int c0 = 0; c0 < deg; c0 += 128) {
        int clen = min(128, deg - c0);
        if (t < clen) ssrc[t] = g_srcs[base + c0 + t];
        __syncthreads();
        if (t < clen) {
            int s = ssrc[t];
#pragma unroll
            for (int hh = 0; hh < 8; hh++) {
                w1s[t * 8 + hh] = __expf(lrelu(afn[hh] + g_af[s * 8 + hh]));
                w2s[t * 8 + hh] = __expf(lrelu(agn[hh] + g_ag[s * 8 + hh]));
            }
        }
        __syncthreads();
#pragma unroll 4
        for (int e = 0; e < clen; e++) {
            int s = ssrc[e];
            float w1v = w1s[e * 8 + h];
            float w2v = w2s[e * 8 + h];
            float2 xv = *(const float2*)&g_xl[(size_t)s * FDIM + colg];
            float2 gv = *(const float2*)&g_gf[s * GHD + c2];
            accf.x += w2v * xv.x; accf.y += w2v * xv.y;
            accg.x += w1v * gv.x; accg.y += w1v * gv.y;
            s1p += w1v; s2p += w2v;
        }
        __syncthreads();
    }

    if (lane == 0) { s12[h] = s1p; s12[8 + h] = s2p; }
    __syncthreads();

    float i1 = 1.f / s12[h], i2 = 1.f / s12[8 + h];
    // feature epilogue: normalize, relu, h1@W2+b2
    float o0 = fmaxf(accf.x * i2 + bias1f[colg], 0.f);
    float o1 = fmaxf(accf.y * i2 + bias1f[colg + 1], 0.f);
    float v = o0 * W2[colg] + o1 * W2[colg + 1];
#pragma unroll
    for (int off = 16; off; off >>= 1) v += __shfl_down_sync(0xffffffffu, v, off);
    if (lane == 0) red[h] = v;
    // gene epilogue: per-head normalized partials
    gacc[h][c2] = accg.x * i1;
    gacc[h][c2 + 1] = accg.y * i1;
    __syncthreads();
    if (t < 8) {
        float r = red[t];
        r += __shfl_down_sync(0x000000ffu, r, 4);
        r += __shfl_down_sync(0x000000ffu, r, 2);
        r += __shfl_down_sync(0x000000ffu, r, 1);
        if (t == 0) g_xl2[n] = r + b2[0];
    }
    float gvv = 0.f;
    if (t < 64) {
        float g1 = 0.f;
#pragma unroll
        for (int hh = 0; hh < 8; hh++) g1 += gacc[hh][t];
        g1 = fmaxf(g1 * 0.125f + bias1g[t], 0.f);
        gvv = g1 * fc2w[t];
#pragma unroll
        for (int off = 16; off; off >>= 1) gvv += __shfl_down_sync(0xffffffffu, gvv, off);
    }
    __syncthreads();
    if (t < 64 && lane == 0) red[h] = gvv;   // warps 0,1 -> red[0],red[1]
    __syncthreads();
    if (t == 0) g_gf2[n] = red[0] + red[1] + fc2b[0];
}

// ---------------- layer 2: single-pass + final sigmoid, warp per node ----------------
// Also resets g_cnt[n] = 0 for the next graph replay (determinism).
__global__ void k_agg2(float* __restrict__ out,
                       const float* __restrict__ att2f, const float* __restrict__ att2g,
                       const float* __restrict__ bias2f, const float* __restrict__ bias2g) {
    int gwarp = (blockIdx.x * blockDim.x + threadIdx.x) >> 5;
    int lane = threadIdx.x & 31;
    if (gwarp >= NN) return;
    int n = gwarp;
    if (lane == 1) g_cnt[n] = 0;   // reset histogram for next replay
    float taf = att2f[0], tag = att2g[0];
    int base = g_rowptr[n], deg = g_rowptr[n + 1] - base;
    float xn = g_xl2[n], gn = g_gf2[n];
    float s1 = 0.f, s2 = 0.f, hf = 0.f, hg = 0.f;
    for (int e = lane; e < deg; e += 32) {
        int s = g_srcs[base + e];
        float xs = g_xl2[s], gs = g_gf2[s];
        float e1 = __expf(lrelu(taf * (xn + xs)));
        float e2 = __expf(lrelu(tag * (gn + gs)));
        s1 += e1; s2 += e2;
        hf += e2 * xs;   // feature msg weighted by gene attention
        hg += e1 * gs;   // gene msg weighted by feature attention
    }
#pragma unroll
    for (int off = 16; off; off >>= 1) {
        s1 += __shfl_xor_sync(0xffffffffu, s1, off);
        s2 += __shfl_xor_sync(0xffffffffu, s2, off);
        hf += __shfl_xor_sync(0xffffffffu, hf, off);
        hg += __shfl_xor_sync(0xffffffffu, hg, off);
    }
    if (lane == 0) {
        float h2  = hf / s2 + bias2f[0];
        float gf3 = hg / s1 + bias2g[0];
        float z = h2 + gf3;
        out[n] = 1.f / (1.f + __expf(-z));
    }
}

// ---------------- launcher: single stream ----------------
extern "C" void kernel_launch(void* const* d_in, const int* in_sizes, int n_in,
                              void* d_out, int out_size) {
    const float* x      = (const float*)d_in[0];
    const float* gfin   = (const float*)d_in[1];
    const int*   ei     = (const int*)d_in[2];
    const float* cjw    = (const float*)d_in[3];
    const float* cjb    = (const float*)d_in[4];
    const float* cj2w   = (const float*)d_in[5];
    const float* cj2b   = (const float*)d_in[6];
    const float* fc1w   = (const float*)d_in[7];
    const float* fc1b   = (const float*)d_in[8];
    const float* fc2w   = (const float*)d_in[9];
    const float* fc2b   = (const float*)d_in[10];
    const float* W1     = (const float*)d_in[11];
    const float* b1     = (const float*)d_in[12];
    const float* att1f  = (const float*)d_in[13];
    const float* att1g  = (const float*)d_in[14];
    const float* bias1f = (const float*)d_in[15];
    const float* bias1g = (const float*)d_in[16];
    const float* W2     = (const float*)d_in[17];
    const float* b2     = (const float*)d_in[18];
    const float* att2f  = (const float*)d_in[19];
    const float* att2g  = (const float*)d_in[20];
    const float* bias2f = (const float*)d_in[21];
    const float* bias2g = (const float*)d_in[22];
    float* out = (float*)d_out;

    static bool attrSet = false;
    if (!attrSet) {
        cudaFuncSetAttribute(k_convgemm, cudaFuncAttributeMaxDynamicSharedMemorySize,
                             SMEM_FLOATS * 4);
        attrSet = true;
    }

    // order chosen so k_convgemm is the 4th launch (ncu capture slot)
    k_hist<<<(EE + 255) / 256, 256>>>(ei);
    k_scan<<<1, 1024>>>();
    k_scatter<<<(ETOT + 255) / 256, 256>>>(ei);
    k_convgemm<<<NBLK, 256, SMEM_FLOATS * 4>>>(x, cjw, cjb, cj2w, cj2b, W1, b1, att1f);
    k_gf<<<NN / 4, 256>>>(gfin, fc1w, fc1b, att1g);
    k_agg1<<<NN, 256>>>(bias1f, bias1g, W2, b2, fc2w, fc2b);
    k_agg2<<<(NN * 32 + 255) / 256, 256>>>(out, att2f, att2g, bias2f, bias2g);
}